// round 10
// baseline (speedup 1.0000x reference)
#include <cuda_runtime.h>

#define N_NODES 100000
#define N_EDGES 1000000
#define D 64
#define CAP 16            // bucket row = 128B = one L2 line; buckets = 12.8 MB
#define OVF_CAP 32768     // E[overflow edges] ~ 5.5k for Poisson(10) tail past 16

// ---------------------------------------------------------------------------
// Scratch (__device__ globals: allocation-free rule)
// ---------------------------------------------------------------------------
__device__ unsigned long long g_buckets[(size_t)N_NODES * CAP];  // 12.8 MB
__device__ int g_cnt[N_NODES];
__device__ int g_ovf_cnt;
__device__ int g_ovf_src[OVF_CAP];
__device__ int g_ovf_dst[OVF_CAP];
__device__ float g_ovf_w[OVF_CAP];

// ---------------------------------------------------------------------------
// K0: zero per-destination counters + overflow cursor
// ---------------------------------------------------------------------------
__global__ void zero_kernel() {
    int i = blockIdx.x * blockDim.x + threadIdx.x;
    if (i < N_NODES) g_cnt[i] = 0;
    if (i == 0) g_ovf_cnt = 0;
}

// ---------------------------------------------------------------------------
// K1: bucket fill — one thread per edge, int32 atomics only. Edges past CAP
// spill to the overflow list (handled post-GEMM via linearity).
// ---------------------------------------------------------------------------
__global__ void fill_kernel(const int* __restrict__ edge_index,
                            const float* __restrict__ edge_weight) {
    int e = blockIdx.x * blockDim.x + threadIdx.x;
    if (e >= N_EDGES) return;
    int src = edge_index[e];
    int dst = edge_index[N_EDGES + e];
    float w = edge_weight[e];
    int pos = atomicAdd(&g_cnt[dst], 1);
    if (pos < CAP) {
        unsigned long long pair = (unsigned long long)(unsigned)src |
                                  ((unsigned long long)__float_as_uint(w) << 32);
        g_buckets[(size_t)dst * CAP + pos] = pair;
    } else {
        int o = atomicAdd(&g_ovf_cnt, 1);
        if (o < OVF_CAP) {
            g_ovf_src[o] = src;
            g_ovf_dst[o] = dst;
            g_ovf_w[o] = w;
        }
    }
}

// ---------------------------------------------------------------------------
// K2 (fused): per 8-node tile:
//   Phase A — warp w accumulates node row (residual + bucketed messages) into
//             registers (lane owns 2 floats), writes to smem.
//   Phase B — classic register-W GEMM: thread (tx,ty) computes out[row][tx]
//             with W row tx held in 64 regs, packed fma.rn.f32x2.
// No g_agg round-trip, no separate GEMM kernel, no float atomics.
// ---------------------------------------------------------------------------
__global__ void __launch_bounds__(256, 2)
fused_kernel(const float* __restrict__ feat,
             const float* __restrict__ W,
             const float* __restrict__ b,
             float* __restrict__ out) {
    __shared__ float arow[8][D];

    const int t = threadIdx.x;
    const int warp = t >> 5;
    const int lane = t & 31;
    const int tx = t & 63;   // phase B: output column
    const int ty = t >> 6;   // phase B: row slot (0..3), handles rows ty, ty+4

    // W row tx in registers as 32 packed float2 (16 KB per CTA from L1/L2)
    unsigned long long wreg[D / 2];
    const unsigned long long* Wp = (const unsigned long long*)(W + (size_t)tx * D);
#pragma unroll
    for (int j = 0; j < D / 2; j++) wreg[j] = Wp[j];
    const float bias = b[tx];

    const float2* __restrict__ f2 = (const float2*)feat;

    // 100000 % 8 == 0: every tile is full.
    for (int base = blockIdx.x * 8; base < N_NODES; base += gridDim.x * 8) {
        // ---- Phase A: accumulate node (base + warp) ----
        const int node = base + warp;
        float2 acc = f2[(size_t)node * 32 + lane];  // residual

        int c = g_cnt[node];
        if (c > CAP) c = CAP;

        unsigned long long mypair =
            (lane < CAP) ? g_buckets[(size_t)node * CAP + lane] : 0ULL;

        int i = 0;
        for (; i + 4 <= c; i += 4) {
            unsigned long long p0 = __shfl_sync(0xffffffffu, mypair, i);
            unsigned long long p1 = __shfl_sync(0xffffffffu, mypair, i + 1);
            unsigned long long p2 = __shfl_sync(0xffffffffu, mypair, i + 2);
            unsigned long long p3 = __shfl_sync(0xffffffffu, mypair, i + 3);
            float2 v0 = f2[(size_t)(unsigned)p0 * 32 + lane];
            float2 v1 = f2[(size_t)(unsigned)p1 * 32 + lane];
            float2 v2 = f2[(size_t)(unsigned)p2 * 32 + lane];
            float2 v3 = f2[(size_t)(unsigned)p3 * 32 + lane];
            float w0 = __uint_as_float((unsigned)(p0 >> 32));
            float w1 = __uint_as_float((unsigned)(p1 >> 32));
            float w2 = __uint_as_float((unsigned)(p2 >> 32));
            float w3 = __uint_as_float((unsigned)(p3 >> 32));
            acc.x = fmaf(w0, v0.x, acc.x); acc.y = fmaf(w0, v0.y, acc.y);
            acc.x = fmaf(w1, v1.x, acc.x); acc.y = fmaf(w1, v1.y, acc.y);
            acc.x = fmaf(w2, v2.x, acc.x); acc.y = fmaf(w2, v2.y, acc.y);
            acc.x = fmaf(w3, v3.x, acc.x); acc.y = fmaf(w3, v3.y, acc.y);
        }
        for (; i < c; i++) {
            unsigned long long p0 = __shfl_sync(0xffffffffu, mypair, i);
            float2 v0 = f2[(size_t)(unsigned)p0 * 32 + lane];
            float w0 = __uint_as_float((unsigned)(p0 >> 32));
            acc.x = fmaf(w0, v0.x, acc.x);
            acc.y = fmaf(w0, v0.y, acc.y);
        }
        ((float2*)arow[warp])[lane] = acc;
        __syncthreads();

        // ---- Phase B: GEMM on the 8 staged rows ----
#pragma unroll
        for (int rr = 0; rr < 2; rr++) {
            const int r = ty + rr * 4;
            unsigned long long acc2 = 0ULL;
            const unsigned long long* ap = (const unsigned long long*)arow[r];
#pragma unroll
            for (int j = 0; j < D / 2; j++) {
                asm("fma.rn.f32x2 %0, %1, %2, %3;"
                    : "=l"(acc2)
                    : "l"(ap[j]), "l"(wreg[j]), "l"(acc2));
            }
            float lo = __uint_as_float((unsigned)acc2);
            float hi = __uint_as_float((unsigned)(acc2 >> 32));
            out[(size_t)(base + r) * D + tx] = lo + hi + bias;
        }
        __syncthreads();  // protect arow before next tile's phase A
    }
}

// ---------------------------------------------------------------------------
// K3: overflow edges, pushed through the linear layer directly:
//   out[dst] += w * (feat[src] @ W^T)      (runs AFTER fused kernel)
// Warp per edge; lane computes output cols lane and lane+32.
// ---------------------------------------------------------------------------
__global__ void overflow_kernel(const float* __restrict__ feat,
                                const float* __restrict__ W,
                                float* __restrict__ out) {
    int n = g_ovf_cnt;
    if (n > OVF_CAP) n = OVF_CAP;
    int gwarp = (blockIdx.x * blockDim.x + threadIdx.x) >> 5;
    int lane = threadIdx.x & 31;
    int nwarps = (gridDim.x * blockDim.x) >> 5;

    for (int e = gwarp; e < n; e += nwarps) {
        int s = g_ovf_src[e], d = g_ovf_dst[e];
        float w = g_ovf_w[e];
        float a0 = 0.f, a1 = 0.f;
#pragma unroll
        for (int k = 0; k < D; k++) {
            float fv = __ldg(&feat[(size_t)s * D + k]);  // broadcast in warp
            a0 = fmaf(fv, __ldg(&W[(size_t)lane * D + k]), a0);
            a1 = fmaf(fv, __ldg(&W[(size_t)(lane + 32) * D + k]), a1);
        }
        atomicAdd(&out[(size_t)d * D + lane], w * a0);
        atomicAdd(&out[(size_t)d * D + lane + 32], w * a1);
    }
}

// ---------------------------------------------------------------------------
extern "C" void kernel_launch(void* const* d_in, const int* in_sizes, int n_in,
                              void* d_out, int out_size) {
    const float* features = (const float*)d_in[0];
    const int* edge_index = (const int*)d_in[1];
    const float* edge_weight = (const float*)d_in[2];
    const float* W = (const float*)d_in[3];
    const float* b = (const float*)d_in[4];
    float* out = (float*)d_out;

    zero_kernel<<<(N_NODES + 255) / 256, 256>>>();
    fill_kernel<<<(N_EDGES + 255) / 256, 256>>>(edge_index, edge_weight);
    fused_kernel<<<1184, 256>>>(features, W, b, out);
    overflow_kernel<<<64, 256>>>(features, W, out);
}

// round 11
// speedup vs baseline: 1.3690x; 1.3690x over previous
#include <cuda_runtime.h>

#define N_NODES 100000
#define N_EDGES 1000000
#define D 64

// Transformed features Y = feat @ W^T  (25.6 MB scratch)
__device__ float g_Y[(size_t)N_NODES * D];

// ---------------------------------------------------------------------------
// K1: Y = feat @ W^T ; out = Y + b   (residual + bias folded, no init pass)
// thread x = output column (W row in 64 regs, packed f32x2), y = row slot.
// ---------------------------------------------------------------------------
__global__ void __launch_bounds__(256)
gemm_kernel(const float* __restrict__ feat,
            const float* __restrict__ W,
            const float* __restrict__ b,
            float* __restrict__ out) {
    __shared__ float arow[4][D];

    const int tx = threadIdx.x;  // 0..63 output column
    const int ty = threadIdx.y;  // 0..3 row slot

    unsigned long long wreg[D / 2];
    const unsigned long long* Wp = (const unsigned long long*)(W + (size_t)tx * D);
#pragma unroll
    for (int j = 0; j < D / 2; j++) wreg[j] = Wp[j];
    const float bias = b[tx];

    for (int row = blockIdx.x * 4 + ty; row < N_NODES; row += gridDim.x * 4) {
        arow[ty][tx] = feat[(size_t)row * D + tx];
        __syncthreads();

        unsigned long long acc2 = 0ULL;
        const unsigned long long* ap = (const unsigned long long*)arow[ty];
#pragma unroll
        for (int j = 0; j < D / 2; j++) {
            asm("fma.rn.f32x2 %0, %1, %2, %3;"
                : "=l"(acc2)
                : "l"(ap[j]), "l"(wreg[j]), "l"(acc2));
        }
        float y = __uint_as_float((unsigned)acc2) +
                  __uint_as_float((unsigned)(acc2 >> 32));
        g_Y[(size_t)row * D + tx] = y;
        out[(size_t)row * D + tx] = y + bias;
        __syncthreads();
    }
}

// ---------------------------------------------------------------------------
// K2: out[dst] += w * Y[src]   for edges whose src is in [src_lo, src_hi).
// 16 threads/edge, one red.global.add.v4.f32 (16B) per thread. Two passes
// partition the gather working set (12.8 MB/pass) to pin it in L2 next to
// the 25.6 MB REDG target region.
// ---------------------------------------------------------------------------
__global__ void __launch_bounds__(256)
scatter_kernel(const int* __restrict__ edge_index,
               const float* __restrict__ edge_weight,
               float* __restrict__ out,
               int src_lo, int src_hi) {
    int t = blockIdx.x * blockDim.x + threadIdx.x;
    int edge = t >> 4;
    int lane = t & 15;
    if (edge >= N_EDGES) return;

    int src = edge_index[edge];
    if (src < src_lo || src >= src_hi) return;

    int dst = edge_index[N_EDGES + edge];
    float w = edge_weight[edge];

    float4 v = reinterpret_cast<const float4*>(g_Y + (size_t)src * D)[lane];
    v.x *= w; v.y *= w; v.z *= w; v.w *= w;

    float* p = out + (size_t)dst * D + lane * 4;
    asm volatile("red.global.add.v4.f32 [%0], {%1, %2, %3, %4};"
                 :: "l"(p), "f"(v.x), "f"(v.y), "f"(v.z), "f"(v.w)
                 : "memory");
}

// ---------------------------------------------------------------------------
extern "C" void kernel_launch(void* const* d_in, const int* in_sizes, int n_in,
                              void* d_out, int out_size) {
    const float* features = (const float*)d_in[0];
    const int* edge_index = (const int*)d_in[1];
    const float* edge_weight = (const float*)d_in[2];
    const float* W = (const float*)d_in[3];
    const float* b = (const float*)d_in[4];
    float* out = (float*)d_out;

    dim3 gblock(64, 4);
    gemm_kernel<<<1480, gblock>>>(features, W, b, out);

    const int nthreads = N_EDGES * 16;
    const int nblocks = (nthreads + 255) / 256;
    scatter_kernel<<<nblocks, 256>>>(edge_index, edge_weight, out,
                                     0, N_NODES / 2);
    scatter_kernel<<<nblocks, 256>>>(edge_index, edge_weight, out,
                                     N_NODES / 2, N_NODES);
}

// round 12
// speedup vs baseline: 1.8952x; 1.3844x over previous
#include <cuda_runtime.h>

#define N_NODES 100000
#define N_EDGES 1000000
#define D 64
#define TILE_ROWS 16
#define N_TILES (N_NODES / TILE_ROWS)   // 6250 exact
#define GEMM_GRID 296                   // 2 blocks/SM * 148 SM, single wave

// Transformed features Y = feat @ W^T  (25.6 MB scratch)
__device__ float g_Y[(size_t)N_NODES * D];

// ---------------------------------------------------------------------------
// K1: Y = feat @ W^T ; out = Y + b   (residual+bias folded into out init)
// 16-row tiles; thread (tx,ty) computes 4 rows x 1 col with 4 independent
// fma.rn.f32x2 chains; next tile prefetched into regs during compute.
// ---------------------------------------------------------------------------
__global__ void __launch_bounds__(256)
gemm_kernel(const float* __restrict__ feat,
            const float* __restrict__ W,
            const float* __restrict__ b,
            float* __restrict__ out) {
    __shared__ float arow[TILE_ROWS][D];

    const int t = threadIdx.x;
    const int tx = t & 63;   // output column
    const int ty = t >> 6;   // 0..3 -> rows 4*ty .. 4*ty+3

    // W row tx in registers (32 packed float2)
    unsigned long long wreg[D / 2];
    const unsigned long long* Wp = (const unsigned long long*)(W + (size_t)tx * D);
#pragma unroll
    for (int j = 0; j < D / 2; j++) wreg[j] = Wp[j];
    const float bias = b[tx];

    // tile-load assignment: thread t loads float4 #t of the 256-float4 tile
    const int lr = t >> 4;   // row 0..15
    const int lc = t & 15;   // float4 segment 0..15

    int tile = blockIdx.x;
    float4 pre;
    if (tile < N_TILES)
        pre = ((const float4*)feat)[((size_t)tile * TILE_ROWS + lr) * 16 + lc];

    for (; tile < N_TILES; tile += GEMM_GRID) {
        ((float4*)arow[lr])[lc] = pre;
        __syncthreads();

        // prefetch next tile (overlaps with compute below)
        int ntile = tile + GEMM_GRID;
        if (ntile < N_TILES)
            pre = ((const float4*)feat)[((size_t)ntile * TILE_ROWS + lr) * 16 + lc];

        const ulonglong2* p0 = (const ulonglong2*)arow[ty * 4 + 0];
        const ulonglong2* p1 = (const ulonglong2*)arow[ty * 4 + 1];
        const ulonglong2* p2 = (const ulonglong2*)arow[ty * 4 + 2];
        const ulonglong2* p3 = (const ulonglong2*)arow[ty * 4 + 3];

        unsigned long long a0 = 0ULL, a1 = 0ULL, a2 = 0ULL, a3 = 0ULL;
#pragma unroll
        for (int j = 0; j < D / 4; j++) {  // 16 x LDS.128 per row
            ulonglong2 q0 = p0[j];
            ulonglong2 q1 = p1[j];
            ulonglong2 q2 = p2[j];
            ulonglong2 q3 = p3[j];
            unsigned long long w0 = wreg[2 * j], w1 = wreg[2 * j + 1];
            asm("fma.rn.f32x2 %0, %1, %2, %0;" : "+l"(a0) : "l"(q0.x), "l"(w0));
            asm("fma.rn.f32x2 %0, %1, %2, %0;" : "+l"(a1) : "l"(q1.x), "l"(w0));
            asm("fma.rn.f32x2 %0, %1, %2, %0;" : "+l"(a2) : "l"(q2.x), "l"(w0));
            asm("fma.rn.f32x2 %0, %1, %2, %0;" : "+l"(a3) : "l"(q3.x), "l"(w0));
            asm("fma.rn.f32x2 %0, %1, %2, %0;" : "+l"(a0) : "l"(q0.y), "l"(w1));
            asm("fma.rn.f32x2 %0, %1, %2, %0;" : "+l"(a1) : "l"(q1.y), "l"(w1));
            asm("fma.rn.f32x2 %0, %1, %2, %0;" : "+l"(a2) : "l"(q2.y), "l"(w1));
            asm("fma.rn.f32x2 %0, %1, %2, %0;" : "+l"(a3) : "l"(q3.y), "l"(w1));
        }

        const size_t rbase = (size_t)tile * TILE_ROWS + ty * 4;
        float y0 = __uint_as_float((unsigned)a0) + __uint_as_float((unsigned)(a0 >> 32));
        float y1 = __uint_as_float((unsigned)a1) + __uint_as_float((unsigned)(a1 >> 32));
        float y2 = __uint_as_float((unsigned)a2) + __uint_as_float((unsigned)(a2 >> 32));
        float y3 = __uint_as_float((unsigned)a3) + __uint_as_float((unsigned)(a3 >> 32));
        g_Y[(rbase + 0) * D + tx] = y0;
        g_Y[(rbase + 1) * D + tx] = y1;
        g_Y[(rbase + 2) * D + tx] = y2;
        g_Y[(rbase + 3) * D + tx] = y3;
        out[(rbase + 0) * D + tx] = y0 + bias;
        out[(rbase + 1) * D + tx] = y1 + bias;
        out[(rbase + 2) * D + tx] = y2 + bias;
        out[(rbase + 3) * D + tx] = y3 + bias;

        __syncthreads();  // protect arow before next tile's store
    }
}

// ---------------------------------------------------------------------------
// K2: out[dst] += w * Y[src] for src in [src_lo, src_hi). 16 threads/edge,
// one red.global.add.v4.f32 per thread. Two passes keep the 12.8 MB gather
// half L2-resident next to the 25.6 MB REDG target.
// ---------------------------------------------------------------------------
__global__ void __launch_bounds__(256)
scatter_kernel(const int* __restrict__ edge_index,
               const float* __restrict__ edge_weight,
               float* __restrict__ out,
               int src_lo, int src_hi) {
    int t = blockIdx.x * blockDim.x + threadIdx.x;
    int edge = t >> 4;
    int lane = t & 15;
    if (edge >= N_EDGES) return;

    int src = edge_index[edge];
    if (src < src_lo || src >= src_hi) return;

    int dst = edge_index[N_EDGES + edge];
    float w = edge_weight[edge];

    float4 v = reinterpret_cast<const float4*>(g_Y + (size_t)src * D)[lane];
    v.x *= w; v.y *= w; v.z *= w; v.w *= w;

    float* p = out + (size_t)dst * D + lane * 4;
    asm volatile("red.global.add.v4.f32 [%0], {%1, %2, %3, %4};"
                 :: "l"(p), "f"(v.x), "f"(v.y), "f"(v.z), "f"(v.w)
                 : "memory");
}

// ---------------------------------------------------------------------------
extern "C" void kernel_launch(void* const* d_in, const int* in_sizes, int n_in,
                              void* d_out, int out_size) {
    const float* features = (const float*)d_in[0];
    const int* edge_index = (const int*)d_in[1];
    const float* edge_weight = (const float*)d_in[2];
    const float* W = (const float*)d_in[3];
    const float* b = (const float*)d_in[4];
    float* out = (float*)d_out;

    gemm_kernel<<<GEMM_GRID, 256>>>(features, W, b, out);

    const int nblocks = (N_EDGES * 16 + 255) / 256;
    scatter_kernel<<<nblocks, 256>>>(edge_index, edge_weight, out,
                                     0, N_NODES / 2);
    scatter_kernel<<<nblocks, 256>>>(edge_index, edge_weight, out,
                                     N_NODES / 2, N_NODES);
}

// round 15
// speedup vs baseline: 2.5486x; 1.3447x over previous
#include <cuda_runtime.h>

#define N_NODES 100000
#define N_EDGES 1000000
#define D 64
#define CAP 32            // bucket row = 256B; P(deg>=32 | Poisson(10)) ~ 6e-9
#define OVF_CAP 8192
#define TILE_ROWS 16
#define N_TILES (N_NODES / TILE_ROWS)   // 6250 exact
#define GEMM_GRID 296                   // 2 blocks/SM, single wave

// ---------------------------------------------------------------------------
// Scratch
// ---------------------------------------------------------------------------
__device__ float g_Y[(size_t)N_NODES * D];                       // 25.6 MB
__device__ unsigned long long g_buckets[(size_t)N_NODES * CAP];  // 25.6 MB
__device__ int g_cnt[N_NODES];
__device__ int g_ovf_cnt;
__device__ int g_ovf_src[OVF_CAP];
__device__ int g_ovf_dst[OVF_CAP];
__device__ float g_ovf_w[OVF_CAP];

// ---------------------------------------------------------------------------
// K0: zero counters
// ---------------------------------------------------------------------------
__global__ void zero_kernel() {
    int i = blockIdx.x * blockDim.x + threadIdx.x;
    if (i < N_NODES) g_cnt[i] = 0;
    if (i == 0) g_ovf_cnt = 0;
}

// ---------------------------------------------------------------------------
// K1: bucket fill — one thread/edge, int32 atomics only.
// ---------------------------------------------------------------------------
__global__ void fill_kernel(const int* __restrict__ edge_index,
                            const float* __restrict__ edge_weight) {
    int e = blockIdx.x * blockDim.x + threadIdx.x;
    if (e >= N_EDGES) return;
    int src = edge_index[e];
    int dst = edge_index[N_EDGES + e];
    float w = edge_weight[e];
    int pos = atomicAdd(&g_cnt[dst], 1);
    if (pos < CAP) {
        unsigned long long pair = (unsigned long long)(unsigned)src |
                                  ((unsigned long long)__float_as_uint(w) << 32);
        g_buckets[(size_t)dst * CAP + pos] = pair;
    } else {
        int o = atomicAdd(&g_ovf_cnt, 1);
        if (o < OVF_CAP) {
            g_ovf_src[o] = src;
            g_ovf_dst[o] = dst;
            g_ovf_w[o] = w;
        }
    }
}

// ---------------------------------------------------------------------------
// K2: Y = feat @ W^T  (16-row tiles, 4 indep fma.rn.f32x2 chains/thread,
// register prefetch of next tile). Writes only g_Y.
// ---------------------------------------------------------------------------
__global__ void __launch_bounds__(256)
gemm_kernel(const float* __restrict__ feat,
            const float* __restrict__ W) {
    __shared__ float arow[TILE_ROWS][D];

    const int t = threadIdx.x;
    const int tx = t & 63;   // output column
    const int ty = t >> 6;   // 0..3 -> rows 4*ty .. 4*ty+3

    unsigned long long wreg[D / 2];
    const unsigned long long* Wp = (const unsigned long long*)(W + (size_t)tx * D);
#pragma unroll
    for (int j = 0; j < D / 2; j++) wreg[j] = Wp[j];

    const int lr = t >> 4;   // load row 0..15
    const int lc = t & 15;   // float4 segment 0..15

    int tile = blockIdx.x;
    float4 pre;
    if (tile < N_TILES)
        pre = ((const float4*)feat)[((size_t)tile * TILE_ROWS + lr) * 16 + lc];

    for (; tile < N_TILES; tile += GEMM_GRID) {
        ((float4*)arow[lr])[lc] = pre;
        __syncthreads();

        int ntile = tile + GEMM_GRID;
        if (ntile < N_TILES)
            pre = ((const float4*)feat)[((size_t)ntile * TILE_ROWS + lr) * 16 + lc];

        const ulonglong2* p0 = (const ulonglong2*)arow[ty * 4 + 0];
        const ulonglong2* p1 = (const ulonglong2*)arow[ty * 4 + 1];
        const ulonglong2* p2 = (const ulonglong2*)arow[ty * 4 + 2];
        const ulonglong2* p3 = (const ulonglong2*)arow[ty * 4 + 3];

        unsigned long long a0 = 0ULL, a1 = 0ULL, a2 = 0ULL, a3 = 0ULL;
#pragma unroll
        for (int j = 0; j < D / 4; j++) {
            ulonglong2 q0 = p0[j];
            ulonglong2 q1 = p1[j];
            ulonglong2 q2 = p2[j];
            ulonglong2 q3 = p3[j];
            unsigned long long w0 = wreg[2 * j], w1 = wreg[2 * j + 1];
            asm("fma.rn.f32x2 %0, %1, %2, %0;" : "+l"(a0) : "l"(q0.x), "l"(w0));
            asm("fma.rn.f32x2 %0, %1, %2, %0;" : "+l"(a1) : "l"(q1.x), "l"(w0));
            asm("fma.rn.f32x2 %0, %1, %2, %0;" : "+l"(a2) : "l"(q2.x), "l"(w0));
            asm("fma.rn.f32x2 %0, %1, %2, %0;" : "+l"(a3) : "l"(q3.x), "l"(w0));
            asm("fma.rn.f32x2 %0, %1, %2, %0;" : "+l"(a0) : "l"(q0.y), "l"(w1));
            asm("fma.rn.f32x2 %0, %1, %2, %0;" : "+l"(a1) : "l"(q1.y), "l"(w1));
            asm("fma.rn.f32x2 %0, %1, %2, %0;" : "+l"(a2) : "l"(q2.y), "l"(w1));
            asm("fma.rn.f32x2 %0, %1, %2, %0;" : "+l"(a3) : "l"(q3.y), "l"(w1));
        }

        const size_t rbase = (size_t)tile * TILE_ROWS + ty * 4;
        g_Y[(rbase + 0) * D + tx] =
            __uint_as_float((unsigned)a0) + __uint_as_float((unsigned)(a0 >> 32));
        g_Y[(rbase + 1) * D + tx] =
            __uint_as_float((unsigned)a1) + __uint_as_float((unsigned)(a1 >> 32));
        g_Y[(rbase + 2) * D + tx] =
            __uint_as_float((unsigned)a2) + __uint_as_float((unsigned)(a2 >> 32));
        g_Y[(rbase + 3) * D + tx] =
            __uint_as_float((unsigned)a3) + __uint_as_float((unsigned)(a3 >> 32));

        __syncthreads();
    }
}

// ---------------------------------------------------------------------------
// K3: warp-per-destination: out[dst] = Y[dst] + b + sum_bucket w*Y[src].
// One coalesced LDG.64 pulls the 256B bucket row (lane i = pair i), pairs
// broadcast via shfl; 4-way unrolled independent gathers. No float atomics.
// ---------------------------------------------------------------------------
__global__ void __launch_bounds__(256)
accum_kernel(const float* __restrict__ b,
             float* __restrict__ out) {
    int gwarp = (blockIdx.x * blockDim.x + threadIdx.x) >> 5;
    int lane = threadIdx.x & 31;
    if (gwarp >= N_NODES) return;
    const int dst = gwarp;

    const float2* __restrict__ y2 = (const float2*)g_Y;
    float2 bias = ((const float2*)b)[lane];
    float2 acc = y2[(size_t)dst * 32 + lane];  // residual Y[dst]

    int c = g_cnt[dst];
    if (c > CAP) c = CAP;

    unsigned long long mypair = g_buckets[(size_t)dst * CAP + lane];

    int i = 0;
    for (; i + 4 <= c; i += 4) {
        unsigned long long p0 = __shfl_sync(0xffffffffu, mypair, i);
        unsigned long long p1 = __shfl_sync(0xffffffffu, mypair, i + 1);
        unsigned long long p2 = __shfl_sync(0xffffffffu, mypair, i + 2);
        unsigned long long p3 = __shfl_sync(0xffffffffu, mypair, i + 3);
        float2 v0 = y2[(size_t)(unsigned)p0 * 32 + lane];
        float2 v1 = y2[(size_t)(unsigned)p1 * 32 + lane];
        float2 v2 = y2[(size_t)(unsigned)p2 * 32 + lane];
        float2 v3 = y2[(size_t)(unsigned)p3 * 32 + lane];
        float w0 = __uint_as_float((unsigned)(p0 >> 32));
        float w1 = __uint_as_float((unsigned)(p1 >> 32));
        float w2 = __uint_as_float((unsigned)(p2 >> 32));
        float w3 = __uint_as_float((unsigned)(p3 >> 32));
        acc.x = fmaf(w0, v0.x, acc.x); acc.y = fmaf(w0, v0.y, acc.y);
        acc.x = fmaf(w1, v1.x, acc.x); acc.y = fmaf(w1, v1.y, acc.y);
        acc.x = fmaf(w2, v2.x, acc.x); acc.y = fmaf(w2, v2.y, acc.y);
        acc.x = fmaf(w3, v3.x, acc.x); acc.y = fmaf(w3, v3.y, acc.y);
    }
    for (; i < c; i++) {
        unsigned long long p0 = __shfl_sync(0xffffffffu, mypair, i);
        float2 v0 = y2[(size_t)(unsigned)p0 * 32 + lane];
        float w0 = __uint_as_float((unsigned)(p0 >> 32));
        acc.x = fmaf(w0, v0.x, acc.x);
        acc.y = fmaf(w0, v0.y, acc.y);
    }
    acc.x += bias.x;
    acc.y += bias.y;
    ((float2*)out)[(size_t)dst * 32 + lane] = acc;
}

// ---------------------------------------------------------------------------
// K4: overflow edges in Y-space: out[dst] += w * Y[src]. Expected empty.
// ---------------------------------------------------------------------------
__global__ void overflow_kernel(float* __restrict__ out) {
    int n = g_ovf_cnt;
    if (n > OVF_CAP) n = OVF_CAP;
    int gwarp = (blockIdx.x * blockDim.x + threadIdx.x) >> 5;
    int lane = threadIdx.x & 31;
    int nwarps = (gridDim.x * blockDim.x) >> 5;
    for (int e = gwarp; e < n; e += nwarps) {
        int s = g_ovf_src[e], d = g_ovf_dst[e];
        float w = g_ovf_w[e];
        float2 v = ((const float2*)g_Y)[(size_t)s * 32 + lane];
        atomicAdd(&out[(size_t)d * D + 2 * lane], w * v.x);
        atomicAdd(&out[(size_t)d * D + 2 * lane + 1], w * v.y);
    }
}

// ---------------------------------------------------------------------------
extern "C" void kernel_launch(void* const* d_in, const int* in_sizes, int n_in,
                              void* d_out, int out_size) {
    const float* features = (const float*)d_in[0];
    const int* edge_index = (const int*)d_in[1];
    const float* edge_weight = (const float*)d_in[2];
    const float* W = (const float*)d_in[3];
    const float* b = (const float*)d_in[4];
    float* out = (float*)d_out;

    zero_kernel<<<(N_NODES + 255) / 256, 256>>>();
    fill_kernel<<<(N_EDGES + 255) / 256, 256>>>(edge_index, edge_weight);
    gemm_kernel<<<GEMM_GRID, 256>>>(features, W);
    accum_kernel<<<(N_NODES * 32 + 255) / 256, 256>>>(b, out);
    overflow_kernel<<<32, 256>>>(out);
}

// round 17
// speedup vs baseline: 2.6085x; 1.0235x over previous
#include <cuda_runtime.h>

#define N_NODES 100000
#define N_EDGES 1000000
#define D 64
#define CAP 32            // bucket row = 256B; P(deg>=32 | Poisson(10)) ~ 6e-9
#define OVF_CAP 8192
#define TILE_ROWS 16
#define N_TILES (N_NODES / TILE_ROWS)   // 6250 exact
#define GEMM_GRID 888                   // 6 blocks/SM * 148 SM, single wave

// ---------------------------------------------------------------------------
// Scratch
// ---------------------------------------------------------------------------
__device__ float g_Y[(size_t)N_NODES * D];                       // 25.6 MB
__device__ unsigned long long g_buckets[(size_t)N_NODES * CAP];  // 25.6 MB
__device__ int g_cnt[N_NODES];
__device__ int g_ovf_cnt;
__device__ int g_ovf_src[OVF_CAP];
__device__ int g_ovf_dst[OVF_CAP];
__device__ float g_ovf_w[OVF_CAP];

// ---------------------------------------------------------------------------
// K0: zero counters
// ---------------------------------------------------------------------------
__global__ void zero_kernel() {
    int i = blockIdx.x * blockDim.x + threadIdx.x;
    if (i < N_NODES) g_cnt[i] = 0;
    if (i == 0) g_ovf_cnt = 0;
}

// ---------------------------------------------------------------------------
// K1: bucket fill — one thread/edge, int32 atomics only.
// ---------------------------------------------------------------------------
__global__ void fill_kernel(const int* __restrict__ edge_index,
                            const float* __restrict__ edge_weight) {
    int e = blockIdx.x * blockDim.x + threadIdx.x;
    if (e >= N_EDGES) return;
    int src = edge_index[e];
    int dst = edge_index[N_EDGES + e];
    float w = edge_weight[e];
    int pos = atomicAdd(&g_cnt[dst], 1);
    if (pos < CAP) {
        unsigned long long pair = (unsigned long long)(unsigned)src |
                                  ((unsigned long long)__float_as_uint(w) << 32);
        g_buckets[(size_t)dst * CAP + pos] = pair;
    } else {
        int o = atomicAdd(&g_ovf_cnt, 1);
        if (o < OVF_CAP) {
            g_ovf_src[o] = src;
            g_ovf_dst[o] = dst;
            g_ovf_w[o] = w;
        }
    }
}

// ---------------------------------------------------------------------------
// K2: Y = feat @ W^T. W lives in smem (transposed float4 layout, lane-
// contiguous -> conflict-free LDS.128), cutting regs 98 -> ~40 so occupancy
// rises 2 -> 6 blocks/SM. 4 independent fma.rn.f32x2 chains per thread,
// register prefetch of next tile.
// ---------------------------------------------------------------------------
__global__ void __launch_bounds__(256)
gemm_kernel(const float* __restrict__ feat,
            const float* __restrict__ W) {
    __shared__ float arow[TILE_ROWS][D];   // 4 KB
    __shared__ float4 wsm[16][64];         // 16 KB: wsm[j2][c] = W[c][4j2..4j2+3]

    const int t = threadIdx.x;
    const int tx = t & 63;   // output column
    const int ty = t >> 6;   // 0..3 -> rows 4*ty .. 4*ty+3

    // stage W transposed: coalesced gmem read, scattered smem write (once)
    for (int idx = t; idx < 64 * 16; idx += 256) {
        int c = idx >> 4, j2 = idx & 15;
        wsm[j2][c] = ((const float4*)W)[c * 16 + j2];
    }

    const int lr = t >> 4;   // load row 0..15
    const int lc = t & 15;   // float4 segment 0..15

    int tile = blockIdx.x;
    float4 pre;
    if (tile < N_TILES)
        pre = ((const float4*)feat)[((size_t)tile * TILE_ROWS + lr) * 16 + lc];

    for (; tile < N_TILES; tile += GEMM_GRID) {
        ((float4*)arow[lr])[lc] = pre;
        __syncthreads();  // also covers the wsm staging on the first pass

        int ntile = tile + GEMM_GRID;
        if (ntile < N_TILES)
            pre = ((const float4*)feat)[((size_t)ntile * TILE_ROWS + lr) * 16 + lc];

        const ulonglong2* p0 = (const ulonglong2*)arow[ty * 4 + 0];
        const ulonglong2* p1 = (const ulonglong2*)arow[ty * 4 + 1];
        const ulonglong2* p2 = (const ulonglong2*)arow[ty * 4 + 2];
        const ulonglong2* p3 = (const ulonglong2*)arow[ty * 4 + 3];

        unsigned long long a0 = 0ULL, a1 = 0ULL, a2 = 0ULL, a3 = 0ULL;
#pragma unroll
        for (int j2 = 0; j2 < 16; j2++) {
            ulonglong2 wv = *(const ulonglong2*)&wsm[j2][tx];  // vector LDS.128
            ulonglong2 q0 = p0[j2];  // broadcast LDS.128
            ulonglong2 q1 = p1[j2];
            ulonglong2 q2 = p2[j2];
            ulonglong2 q3 = p3[j2];
            asm("fma.rn.f32x2 %0, %1, %2, %0;" : "+l"(a0) : "l"(q0.x), "l"(wv.x));
            asm("fma.rn.f32x2 %0, %1, %2, %0;" : "+l"(a1) : "l"(q1.x), "l"(wv.x));
            asm("fma.rn.f32x2 %0, %1, %2, %0;" : "+l"(a2) : "l"(q2.x), "l"(wv.x));
            asm("fma.rn.f32x2 %0, %1, %2, %0;" : "+l"(a3) : "l"(q3.x), "l"(wv.x));
            asm("fma.rn.f32x2 %0, %1, %2, %0;" : "+l"(a0) : "l"(q0.y), "l"(wv.y));
            asm("fma.rn.f32x2 %0, %1, %2, %0;" : "+l"(a1) : "l"(q1.y), "l"(wv.y));
            asm("fma.rn.f32x2 %0, %1, %2, %0;" : "+l"(a2) : "l"(q2.y), "l"(wv.y));
            asm("fma.rn.f32x2 %0, %1, %2, %0;" : "+l"(a3) : "l"(q3.y), "l"(wv.y));
        }

        const size_t rbase = (size_t)tile * TILE_ROWS + ty * 4;
        g_Y[(rbase + 0) * D + tx] =
            __uint_as_float((unsigned)a0) + __uint_as_float((unsigned)(a0 >> 32));
        g_Y[(rbase + 1) * D + tx] =
            __uint_as_float((unsigned)a1) + __uint_as_float((unsigned)(a1 >> 32));
        g_Y[(rbase + 2) * D + tx] =
            __uint_as_float((unsigned)a2) + __uint_as_float((unsigned)(a2 >> 32));
        g_Y[(rbase + 3) * D + tx] =
            __uint_as_float((unsigned)a3) + __uint_as_float((unsigned)(a3 >> 32));

        __syncthreads();
    }
}

// ---------------------------------------------------------------------------
// K3: warp-per-destination: out[dst] = Y[dst] + b + sum_bucket w*Y[src].
// Coalesced bucket-row load as uint2 (src half / weight half), 32-bit shfl
// broadcasts, 32-bit index math (one IMAD.WIDE per gather), and packed
// fma.rn.f32x2 (1 FMA per gather). No float atomics.
// ---------------------------------------------------------------------------
__global__ void __launch_bounds__(256)
accum_kernel(const float* __restrict__ b,
             float* __restrict__ out) {
    int gwarp = (blockIdx.x * blockDim.x + threadIdx.x) >> 5;
    unsigned lane = threadIdx.x & 31;
    if (gwarp >= N_NODES) return;
    const unsigned dst = gwarp;

    const unsigned long long* __restrict__ yq = (const unsigned long long*)g_Y;
    float2 bias = ((const float2*)b)[lane];

    unsigned long long acc = yq[dst * 32u + lane];  // residual Y[dst]

    int c = g_cnt[dst];
    if (c > CAP) c = CAP;

    // bucket row: lane i holds pair i (src in .x, weight bits in .y)
    uint2 mp = ((const uint2*)g_buckets)[dst * CAP + lane];

    int i = 0;
    for (; i + 4 <= c; i += 4) {
        unsigned s0 = __shfl_sync(0xffffffffu, mp.x, i);
        unsigned s1 = __shfl_sync(0xffffffffu, mp.x, i + 1);
        unsigned s2 = __shfl_sync(0xffffffffu, mp.x, i + 2);
        unsigned s3 = __shfl_sync(0xffffffffu, mp.x, i + 3);
        unsigned w0 = __shfl_sync(0xffffffffu, mp.y, i);
        unsigned w1 = __shfl_sync(0xffffffffu, mp.y, i + 1);
        unsigned w2 = __shfl_sync(0xffffffffu, mp.y, i + 2);
        unsigned w3 = __shfl_sync(0xffffffffu, mp.y, i + 3);
        unsigned long long v0 = yq[s0 * 32u + lane];
        unsigned long long v1 = yq[s1 * 32u + lane];
        unsigned long long v2 = yq[s2 * 32u + lane];
        unsigned long long v3 = yq[s3 * 32u + lane];
        unsigned long long ww0, ww1, ww2, ww3;
        asm("mov.b64 %0, {%1, %1};" : "=l"(ww0) : "r"(w0));
        asm("mov.b64 %0, {%1, %1};" : "=l"(ww1) : "r"(w1));
        asm("mov.b64 %0, {%1, %1};" : "=l"(ww2) : "r"(w2));
        asm("mov.b64 %0, {%1, %1};" : "=l"(ww3) : "r"(w3));
        asm("fma.rn.f32x2 %0, %1, %2, %0;" : "+l"(acc) : "l"(v0), "l"(ww0));
        asm("fma.rn.f32x2 %0, %1, %2, %0;" : "+l"(acc) : "l"(v1), "l"(ww1));
        asm("fma.rn.f32x2 %0, %1, %2, %0;" : "+l"(acc) : "l"(v2), "l"(ww2));
        asm("fma.rn.f32x2 %0, %1, %2, %0;" : "+l"(acc) : "l"(v3), "l"(ww3));
    }
    for (; i < c; i++) {
        unsigned s0 = __shfl_sync(0xffffffffu, mp.x, i);
        unsigned w0 = __shfl_sync(0xffffffffu, mp.y, i);
        unsigned long long v0 = yq[s0 * 32u + lane];
        unsigned long long ww0;
        asm("mov.b64 %0, {%1, %1};" : "=l"(ww0) : "r"(w0));
        asm("fma.rn.f32x2 %0, %1, %2, %0;" : "+l"(acc) : "l"(v0), "l"(ww0));
    }

    float2 r;
    r.x = __uint_as_float((unsigned)acc) + bias.x;
    r.y = __uint_as_float((unsigned)(acc >> 32)) + bias.y;
    ((float2*)out)[dst * 32u + lane] = r;
}

// ---------------------------------------------------------------------------
// K4: overflow edges in Y-space: out[dst] += w * Y[src]. Expected empty.
// ---------------------------------------------------------------------------
__global__ void overflow_kernel(float* __restrict__ out) {
    int n = g_ovf_cnt;
    if (n > OVF_CAP) n = OVF_CAP;
    int gwarp = (blockIdx.x * blockDim.x + threadIdx.x) >> 5;
    int lane = threadIdx.x & 31;
    int nwarps = (gridDim.x * blockDim.x) >> 5;
    for (int e = gwarp; e < n; e += nwarps) {
        int s = g_ovf_src[e], d = g_ovf_dst[e];
        float w = g_ovf_w[e];
        float2 v = ((const float2*)g_Y)[(size_t)s * 32 + lane];
        atomicAdd(&out[(size_t)d * D + 2 * lane], w * v.x);
        atomicAdd(&out[(size_t)d * D + 2 * lane + 1], w * v.y);
    }
}

// ---------------------------------------------------------------------------
extern "C" void kernel_launch(void* const* d_in, const int* in_sizes, int n_in,
                              void* d_out, int out_size) {
    const float* features = (const float*)d_in[0];
    const int* edge_index = (const int*)d_in[1];
    const float* edge_weight = (const float*)d_in[2];
    const float* W = (const float*)d_in[3];
    const float* b = (const float*)d_in[4];
    float* out = (float*)d_out;

    zero_kernel<<<(N_NODES + 255) / 256, 256>>>();
    fill_kernel<<<(N_EDGES + 255) / 256, 256>>>(edge_index, edge_weight);
    gemm_kernel<<<GEMM_GRID, 256>>>(features, W);
    accum_kernel<<<(N_NODES * 32 + 255) / 256, 256>>>(b, out);
    overflow_kernel<<<32, 256>>>(out);
}